// round 1
// baseline (speedup 1.0000x reference)
#include <cuda_runtime.h>
#include <math.h>

// Problem constants
#define BSZ   512
#define SEQ   100
#define DIM   16
#define F48   48
#define NH    36          // activation-unit hidden dim
#define ECOLS 1764        // 48*36 (E) + 36 (c)
#define SK    3600        // SEQ*NH
#define COMB  176

// -------- scratch (__device__ globals: allocation-free) --------
__device__ float g_Ec[BSZ * ECOLS];          // per-batch effective matrix E (1728) + c (36)
__device__ float g_h_skb[SK * BSZ];          // h_pre, [s*36+k][b] layout (for batch stats)
__device__ float g_h_bsk[BSZ * SK];          // h_pre, [b][s*36+k] layout (for scores)
__device__ float g_vs[BSZ * SEQ * F48];      // gathered behavior vectors
__device__ float g_mu_act[SK];
__device__ float g_isr_act[SK];
__device__ float g_x[BSZ * COMB];            // concat(profile, x_inter)
__device__ float g_y1[BSZ * 200];
__device__ float g_mu1[200], g_isr1[200];
__device__ float g_y2[BSZ * 80];
__device__ float g_mu2[80], g_isr2[80];

struct IdPtrs { const int* p[8]; };

// ============================================================================
// K1: build E[b, 48x36] and c[b, 36] as one GEMM  [512 x 48] @ [48 x 1764]
//   E[b,i,k] = sum_j v_item[b,j]*W1[(144+i*48+j)*36+k] + W1[(96+i)*36+k] - W1[(48+i)*36+k]
//   c[b,k]   = b_act1[k] + sum_j v_item[b,j]*(W1[j*36+k] + W1[(48+j)*36+k])
// grid (56, 8), block 256 = 32 cols x 8 row-groups (8 rows each -> 64 b / block)
// ============================================================================
__global__ void k1_EC(const float* __restrict__ table,
                      const int* __restrict__ ig, const int* __restrict__ ish,
                      const int* __restrict__ ic,
                      const float* __restrict__ W1, const float* __restrict__ b1) {
    __shared__ float As[48][64];   // [j][b_local]
    int tid = threadIdx.x;
    int b_base = blockIdx.y * 64;

    // load A tile: v_item[b, j] = embed[ id_{j/16}[b] ][ j%16 ]
    for (int p = tid; p < 48 * 64; p += 256) {
        int j = p >> 6, bl = p & 63;
        int which = j >> 4;
        int b = b_base + bl;
        int id = (which == 0) ? ig[b] : (which == 1) ? ish[b] : ic[b];
        As[j][bl] = table[(size_t)id * DIM + (j & 15)];
    }
    __syncthreads();

    int tx = tid & 31, ty = tid >> 5;
    int col = blockIdx.x * 32 + tx;
    if (col >= ECOLS) return;
    int b0 = ty * 8;

    float acc[8];
#pragma unroll
    for (int r = 0; r < 8; r++) acc[r] = 0.f;

    if (col < 1728) {
        int i = col / 36, k = col - i * 36;
        const float* wp = W1 + (size_t)(144 + i * 48) * 36 + k;
#pragma unroll 4
        for (int j = 0; j < 48; j++) {
            float w = wp[j * 36];
            float4 a0 = *(const float4*)&As[j][b0];
            float4 a1 = *(const float4*)&As[j][b0 + 4];
            acc[0] += w * a0.x; acc[1] += w * a0.y; acc[2] += w * a0.z; acc[3] += w * a0.w;
            acc[4] += w * a1.x; acc[5] += w * a1.y; acc[6] += w * a1.z; acc[7] += w * a1.w;
        }
        float wcb = W1[(96 + i) * 36 + k] - W1[(48 + i) * 36 + k];
#pragma unroll
        for (int r = 0; r < 8; r++) acc[r] += wcb;
    } else {
        int k = col - 1728;
#pragma unroll 4
        for (int j = 0; j < 48; j++) {
            float w = W1[j * 36 + k] + W1[(48 + j) * 36 + k];
            float4 a0 = *(const float4*)&As[j][b0];
            float4 a1 = *(const float4*)&As[j][b0 + 4];
            acc[0] += w * a0.x; acc[1] += w * a0.y; acc[2] += w * a0.z; acc[3] += w * a0.w;
            acc[4] += w * a1.x; acc[5] += w * a1.y; acc[6] += w * a1.z; acc[7] += w * a1.w;
        }
        float bb = b1[k];
#pragma unroll
        for (int r = 0; r < 8; r++) acc[r] += bb;
    }
#pragma unroll
    for (int r = 0; r < 8; r++)
        g_Ec[(size_t)(b_base + b0 + r) * ECOLS + col] = acc[r];
}

// ============================================================================
// K2: per-batch: gather v_series (also store to g_vs), compute
//     h_pre[s,k] = c[k] + sum_i v_series[s,i]*E[i,k]; write both layouts.
// grid 512, block 128. smem: Ec (7KB) + vsT[48][100] (19.2KB)
// ============================================================================
__global__ void k2_hpre(const float* __restrict__ table,
                        const int* __restrict__ vg, const int* __restrict__ vsh,
                        const int* __restrict__ vc) {
    __shared__ float Ec_s[ECOLS];
    __shared__ float vsT[48][SEQ];   // [i][s]
    int b = blockIdx.x;
    int tid = threadIdx.x;

    const float4* src = (const float4*)(g_Ec + (size_t)b * ECOLS);
    for (int p = tid; p < ECOLS / 4; p += 128) ((float4*)Ec_s)[p] = src[p];

    for (int p = tid; p < SEQ * 3; p += 128) {
        int s = p / 3, which = p - s * 3;
        int id = (which == 0) ? vg[b * SEQ + s] : (which == 1) ? vsh[b * SEQ + s] : vc[b * SEQ + s];
        const float4* row = (const float4*)(table + (size_t)id * DIM);
        float4 r0 = row[0], r1 = row[1], r2 = row[2], r3 = row[3];
        int i0 = which * 16;
        vsT[i0 + 0][s] = r0.x; vsT[i0 + 1][s] = r0.y; vsT[i0 + 2][s] = r0.z; vsT[i0 + 3][s] = r0.w;
        vsT[i0 + 4][s] = r1.x; vsT[i0 + 5][s] = r1.y; vsT[i0 + 6][s] = r1.z; vsT[i0 + 7][s] = r1.w;
        vsT[i0 + 8][s] = r2.x; vsT[i0 + 9][s] = r2.y; vsT[i0 +10][s] = r2.z; vsT[i0 +11][s] = r2.w;
        vsT[i0 +12][s] = r3.x; vsT[i0 +13][s] = r3.y; vsT[i0 +14][s] = r3.z; vsT[i0 +15][s] = r3.w;
        float4* dst = (float4*)(g_vs + ((size_t)b * SEQ + s) * F48 + which * 16);
        dst[0] = r0; dst[1] = r1; dst[2] = r2; dst[3] = r3;
    }
    __syncthreads();

    // 25 s-groups (4 s) x 9 k-groups (4 k) = 225 tiles
    for (int t = tid; t < 225; t += 128) {
        int sg = t / 9, k4 = t - sg * 9;
        float4 c4 = *(const float4*)&Ec_s[1728 + k4 * 4];
        float acc[4][4];
#pragma unroll
        for (int si = 0; si < 4; si++) {
            acc[si][0] = c4.x; acc[si][1] = c4.y; acc[si][2] = c4.z; acc[si][3] = c4.w;
        }
#pragma unroll 4
        for (int i = 0; i < 48; i++) {
            float4 v = *(const float4*)&vsT[i][sg * 4];
            float4 e = *(const float4*)&Ec_s[i * 36 + k4 * 4];
            acc[0][0] += v.x * e.x; acc[0][1] += v.x * e.y; acc[0][2] += v.x * e.z; acc[0][3] += v.x * e.w;
            acc[1][0] += v.y * e.x; acc[1][1] += v.y * e.y; acc[1][2] += v.y * e.z; acc[1][3] += v.y * e.w;
            acc[2][0] += v.z * e.x; acc[2][1] += v.z * e.y; acc[2][2] += v.z * e.z; acc[2][3] += v.z * e.w;
            acc[3][0] += v.w * e.x; acc[3][1] += v.w * e.y; acc[3][2] += v.w * e.z; acc[3][3] += v.w * e.w;
        }
#pragma unroll
        for (int si = 0; si < 4; si++) {
            int s = sg * 4 + si;
            float4 v4 = make_float4(acc[si][0], acc[si][1], acc[si][2], acc[si][3]);
            *(float4*)&g_h_bsk[(size_t)b * SK + s * 36 + k4 * 4] = v4;
            int kb = s * 36 + k4 * 4;
            g_h_skb[(size_t)(kb + 0) * BSZ + b] = v4.x;
            g_h_skb[(size_t)(kb + 1) * BSZ + b] = v4.y;
            g_h_skb[(size_t)(kb + 2) * BSZ + b] = v4.z;
            g_h_skb[(size_t)(kb + 3) * BSZ + b] = v4.w;
        }
    }
}

// ============================================================================
// K3: Dice batch stats for activation unit: mean/var over B for each (s,k)
// grid 3600, block 128 (each thread loads exactly one float4 of the 512 row)
// ============================================================================
__global__ void k3_act_stats() {
    int row = blockIdx.x;
    int tid = threadIdx.x;
    float4 v = ((const float4*)(g_h_skb + (size_t)row * BSZ))[tid];
    float s = v.x + v.y + v.z + v.w;
    float q = v.x * v.x + v.y * v.y + v.z * v.z + v.w * v.w;
#pragma unroll
    for (int o = 16; o; o >>= 1) {
        s += __shfl_down_sync(0xffffffffu, s, o);
        q += __shfl_down_sync(0xffffffffu, q, o);
    }
    __shared__ float sh[8];
    int w = tid >> 5;
    if ((tid & 31) == 0) { sh[w] = s; sh[4 + w] = q; }
    __syncthreads();
    if (tid == 0) {
        s = sh[0] + sh[1] + sh[2] + sh[3];
        q = sh[4] + sh[5] + sh[6] + sh[7];
        float mu = s * (1.f / 512.f);
        float var = q * (1.f / 512.f) - mu * mu;
        g_mu_act[row] = mu;
        g_isr_act[row] = rsqrtf(var + 1e-3f);
    }
}

// ============================================================================
// K4: per-batch: dice -> scores -> masked interest sum; gather profile; write x
// grid 512, block 128
// ============================================================================
__global__ void k4_inter(const float* __restrict__ table, IdPtrs ids,
                         const int* __restrict__ vg,
                         const float* __restrict__ alpha,
                         const float* __restrict__ wout,
                         const float* __restrict__ bout) {
    __shared__ float h_s[SK];
    __shared__ float coef[SEQ];
    int b = blockIdx.x;
    int tid = threadIdx.x;

    const float4* src = (const float4*)(g_h_bsk + (size_t)b * SK);
    for (int p = tid; p < SK / 4; p += 128) ((float4*)h_s)[p] = src[p];
    __syncthreads();

    if (tid < SEQ) {
        int s = tid;
        float acc = bout[0];
#pragma unroll 4
        for (int k = 0; k < NH; k++) {
            int idx = s * NH + k;
            float x = h_s[idx];
            float xn = (x - g_mu_act[idx]) * g_isr_act[idx];
            float pp = 1.f / (1.f + expf(-xn));
            float val = x * (pp + alpha[k] * (1.f - pp));
            acc += val * wout[k];
        }
        float m = (vg[b * SEQ + s] == 0) ? 1.f : 0.f;   // NOTE: source keeps PADDING positions
        coef[s] = acc * m;
    }
    __syncthreads();

    if (tid < F48) {
        float a = 0.f;
        const float* vsrow = g_vs + (size_t)b * SEQ * F48 + tid;
#pragma unroll 4
        for (int s = 0; s < SEQ; s++) a += vsrow[s * F48] * coef[s];
        g_x[(size_t)b * COMB + 128 + tid] = a;
    }
    // profile: 8 embeds x 16 dims
    {
        int f = tid;            // 0..127
        int which = f >> 4;
        int id = ids.p[which][b];
        g_x[(size_t)b * COMB + f] = table[(size_t)id * DIM + (f & 15)];
    }
}

// ============================================================================
// K5: MLP1: y1 = LN(x @ W[176,200] + b) ; grid 32 (16 rows each), block 256
// ============================================================================
__global__ void k5_mlp1(const float* __restrict__ W, const float* __restrict__ bias,
                        const float* __restrict__ g, const float* __restrict__ beta) {
    __shared__ float xs[16 * COMB];
    __shared__ float ys[16][200];
    __shared__ float mu_s[16], isr_s[16];
    int tid = threadIdx.x;
    int b0 = blockIdx.x * 16;

    const float4* src = (const float4*)(g_x + (size_t)b0 * COMB);
    for (int p = tid; p < 16 * COMB / 4; p += 256) ((float4*)xs)[p] = src[p];
    __syncthreads();

    if (tid < 200) {
        float acc[16];
        float bb = bias[tid];
#pragma unroll
        for (int r = 0; r < 16; r++) acc[r] = bb;
        for (int j = 0; j < COMB; j++) {
            float w = W[j * 200 + tid];
#pragma unroll
            for (int r = 0; r < 16; r++) acc[r] += w * xs[r * COMB + j];
        }
#pragma unroll
        for (int r = 0; r < 16; r++) ys[r][tid] = acc[r];
    }
    __syncthreads();
    if (tid < 16) {
        float s = 0.f, q = 0.f;
        for (int c = 0; c < 200; c++) { float v = ys[tid][c]; s += v; q += v * v; }
        float mu = s * (1.f / 200.f);
        float var = q * (1.f / 200.f) - mu * mu;
        mu_s[tid] = mu; isr_s[tid] = rsqrtf(var + 1e-3f);
    }
    __syncthreads();
    if (tid < 200) {
        float gg = g[tid], be = beta[tid];
#pragma unroll
        for (int r = 0; r < 16; r++)
            g_y1[(size_t)(b0 + r) * 200 + tid] = (ys[r][tid] - mu_s[r]) * isr_s[r] * gg + be;
    }
}

// ============================================================================
// K6/K8: per-feature batch stats over B (sel 0 -> y1[200], sel 1 -> y2[80])
// ============================================================================
__global__ void k_feat_stats(int sel) {
    const float* src; int Fdim; float* mu; float* isr;
    if (sel == 0) { src = g_y1; Fdim = 200; mu = g_mu1; isr = g_isr1; }
    else          { src = g_y2; Fdim = 80;  mu = g_mu2; isr = g_isr2; }
    int f = blockIdx.x;
    int tid = threadIdx.x;
    float s = 0.f, q = 0.f;
    for (int b = tid; b < BSZ; b += 128) {
        float v = src[(size_t)b * Fdim + f];
        s += v; q += v * v;
    }
#pragma unroll
    for (int o = 16; o; o >>= 1) {
        s += __shfl_down_sync(0xffffffffu, s, o);
        q += __shfl_down_sync(0xffffffffu, q, o);
    }
    __shared__ float sh[8];
    int w = tid >> 5;
    if ((tid & 31) == 0) { sh[w] = s; sh[4 + w] = q; }
    __syncthreads();
    if (tid == 0) {
        s = sh[0] + sh[1] + sh[2] + sh[3];
        q = sh[4] + sh[5] + sh[6] + sh[7];
        float m = s * (1.f / 512.f);
        float var = q * (1.f / 512.f) - m * m;
        mu[f] = m; isr[f] = rsqrtf(var + 1e-3f);
    }
}

// ============================================================================
// K7: MLP2: y2 = LN(dice(y1) @ W[200,80] + b) ; grid 32, block 128
// ============================================================================
__global__ void k7_mlp2(const float* __restrict__ alpha1, const float* __restrict__ W,
                        const float* __restrict__ bias,
                        const float* __restrict__ g, const float* __restrict__ beta) {
    __shared__ float hs[16 * 200];
    __shared__ float ys[16][80];
    __shared__ float mu_s[16], isr_s[16];
    int tid = threadIdx.x;
    int b0 = blockIdx.x * 16;

    for (int p = tid; p < 16 * 200; p += 128) {
        int f = p % 200;
        float v = g_y1[(size_t)b0 * 200 + p];
        float xn = (v - g_mu1[f]) * g_isr1[f];
        float pp = 1.f / (1.f + expf(-xn));
        hs[p] = v * (pp + alpha1[f] * (1.f - pp));
    }
    __syncthreads();

    if (tid < 80) {
        float acc[16];
        float bb = bias[tid];
#pragma unroll
        for (int r = 0; r < 16; r++) acc[r] = bb;
        for (int j = 0; j < 200; j++) {
            float w = W[j * 80 + tid];
#pragma unroll
            for (int r = 0; r < 16; r++) acc[r] += w * hs[r * 200 + j];
        }
#pragma unroll
        for (int r = 0; r < 16; r++) ys[r][tid] = acc[r];
    }
    __syncthreads();
    if (tid < 16) {
        float s = 0.f, q = 0.f;
        for (int c = 0; c < 80; c++) { float v = ys[tid][c]; s += v; q += v * v; }
        float mu = s * (1.f / 80.f);
        float var = q * (1.f / 80.f) - mu * mu;
        mu_s[tid] = mu; isr_s[tid] = rsqrtf(var + 1e-3f);
    }
    __syncthreads();
    if (tid < 80) {
        float gg = g[tid], be = beta[tid];
#pragma unroll
        for (int r = 0; r < 16; r++)
            g_y2[(size_t)(b0 + r) * 80 + tid] = (ys[r][tid] - mu_s[r]) * isr_s[r] * gg + be;
    }
}

// ============================================================================
// K9: out = softmax(dice(y2) @ W[80,2] + b) ; grid 2, block 256
// ============================================================================
__global__ void k9_out(const float* __restrict__ alpha2, const float* __restrict__ W,
                       const float* __restrict__ bout, float* __restrict__ out) {
    int b = blockIdx.x * blockDim.x + threadIdx.x;
    if (b >= BSZ) return;
    float a0 = bout[0], a1 = bout[1];
#pragma unroll 4
    for (int k = 0; k < 80; k++) {
        float v = g_y2[(size_t)b * 80 + k];
        float xn = (v - g_mu2[k]) * g_isr2[k];
        float pp = 1.f / (1.f + expf(-xn));
        float h = v * (pp + alpha2[k] * (1.f - pp));
        a0 += h * W[k * 2];
        a1 += h * W[k * 2 + 1];
    }
    float m = fmaxf(a0, a1);
    float e0 = expf(a0 - m), e1 = expf(a1 - m);
    float inv = 1.f / (e0 + e1);
    out[b * 2] = e0 * inv;
    out[b * 2 + 1] = e1 * inv;
}

// ============================================================================
extern "C" void kernel_launch(void* const* d_in, const int* in_sizes, int n_in,
                              void* d_out, int out_size) {
    (void)in_sizes; (void)n_in; (void)out_size;
    const int* uid  = (const int*)d_in[0];
    const int* ut1  = (const int*)d_in[1];
    const int* ut2  = (const int*)d_in[2];
    const int* ut3  = (const int*)d_in[3];
    const int* ut4  = (const int*)d_in[4];
    const int* ig   = (const int*)d_in[5];
    const int* ish  = (const int*)d_in[6];
    const int* ic   = (const int*)d_in[7];
    const int* vg   = (const int*)d_in[8];
    const int* vsh  = (const int*)d_in[9];
    const int* vc   = (const int*)d_in[10];
    const float* table     = (const float*)d_in[11];
    const float* W_act1    = (const float*)d_in[12];
    const float* b_act1    = (const float*)d_in[13];
    const float* alpha_act = (const float*)d_in[14];
    const float* W_act_out = (const float*)d_in[15];
    const float* b_act_out = (const float*)d_in[16];
    const float* W_mlp1    = (const float*)d_in[17];
    const float* b_mlp1    = (const float*)d_in[18];
    const float* g_ln1     = (const float*)d_in[19];
    const float* beta_ln1  = (const float*)d_in[20];
    const float* alpha_m1  = (const float*)d_in[21];
    const float* W_mlp2    = (const float*)d_in[22];
    const float* b_mlp2    = (const float*)d_in[23];
    const float* g_ln2     = (const float*)d_in[24];
    const float* beta_ln2  = (const float*)d_in[25];
    const float* alpha_m2  = (const float*)d_in[26];
    const float* W_out     = (const float*)d_in[27];
    const float* b_out     = (const float*)d_in[28];
    float* out = (float*)d_out;

    IdPtrs ids;
    ids.p[0] = uid; ids.p[1] = ut1; ids.p[2] = ut2; ids.p[3] = ut3;
    ids.p[4] = ut4; ids.p[5] = ig;  ids.p[6] = ish; ids.p[7] = ic;

    k1_EC<<<dim3(56, 8), 256>>>(table, ig, ish, ic, W_act1, b_act1);
    k2_hpre<<<BSZ, 128>>>(table, vg, vsh, vc);
    k3_act_stats<<<SK, 128>>>();
    k4_inter<<<BSZ, 128>>>(table, ids, vg, alpha_act, W_act_out, b_act_out);
    k5_mlp1<<<32, 256>>>(W_mlp1, b_mlp1, g_ln1, beta_ln1);
    k_feat_stats<<<200, 128>>>(0);
    k7_mlp2<<<32, 128>>>(alpha_m1, W_mlp2, b_mlp2, g_ln2, beta_ln2);
    k_feat_stats<<<80, 128>>>(1);
    k9_out<<<2, 256>>>(alpha_m2, W_out, b_out, out);
}

// round 3
// speedup vs baseline: 1.5825x; 1.5825x over previous
#include <cuda_runtime.h>
#include <math.h>

// Problem constants
#define BSZ   512
#define SEQ   100
#define DIM   16
#define F48   48
#define NH    36
#define ECOLS 1764        // 48*36 (E) + 36 (c)
#define SK    3600        // SEQ*36
#define COMB  176

// -------- scratch (__device__ globals: allocation-free) --------
__device__ float g_Ec[BSZ * ECOLS];
__device__ float g_h_skb[SK * BSZ];     // h_pre [s*36+k][b]; only kept-s rows are valid
__device__ float g_mu_act[SK];          // only kept-s rows valid
__device__ float g_isr_act[SK];
__device__ float g_coef[BSZ * SEQ];     // [b][s] masked scores
__device__ int   g_skeep[SEQ];          // per-s: any b with vg==0
__device__ int   g_any;                 // any kept position at all
__device__ float g_x[BSZ * COMB];
__device__ float g_y1[BSZ * 200];
__device__ float g_mu1[200], g_isr1[200];
__device__ float g_y2[BSZ * 80];
__device__ float g_mu2[80], g_isr2[80];

struct IdPtrs { const int* p[8]; };

// ============================================================================
// K0: per-s keep flag: g_skeep[s] = OR_b (vg[b,s]==0). grid 100, block 128.
// ============================================================================
__global__ void k0_keep(const int* __restrict__ vg) {
    int s = blockIdx.x, t = threadIdx.x;
    int any = 0;
    for (int b = t; b < BSZ; b += 128)
        any |= (vg[b * SEQ + s] == 0);
    unsigned m = __ballot_sync(0xffffffffu, any);
    __shared__ unsigned sh[4];
    if ((t & 31) == 0) sh[t >> 5] = m;
    __syncthreads();
    if (t == 0) g_skeep[s] = (sh[0] | sh[1] | sh[2] | sh[3]) ? 1 : 0;
}

// K0b: g_any = OR_s g_skeep[s]. 1 block.
__global__ void k0b_any() {
    int t = threadIdx.x;
    int v = (t < SEQ) ? g_skeep[t] : 0;
    unsigned m = __ballot_sync(0xffffffffu, v);
    __shared__ unsigned sh[4];
    if ((t & 31) == 0) sh[t >> 5] = m;
    __syncthreads();
    if (t == 0) g_any = (sh[0] | sh[1] | sh[2] | sh[3]) ? 1 : 0;
}

// ============================================================================
// K1: build E[b,48x36] and c[b,36]: [512x48] @ [48x1764]. Early-exit if !g_any.
// grid (56, 8), block 256
// ============================================================================
__global__ void k1_EC(const float* __restrict__ table,
                      const int* __restrict__ ig, const int* __restrict__ ish,
                      const int* __restrict__ ic,
                      const float* __restrict__ W1, const float* __restrict__ b1) {
    if (g_any == 0) return;
    __shared__ float As[48][64];
    int tid = threadIdx.x;
    int b_base = blockIdx.y * 64;

    for (int p = tid; p < 48 * 64; p += 256) {
        int j = p >> 6, bl = p & 63;
        int which = j >> 4;
        int b = b_base + bl;
        int id = (which == 0) ? ig[b] : (which == 1) ? ish[b] : ic[b];
        As[j][bl] = table[(size_t)id * DIM + (j & 15)];
    }
    __syncthreads();

    int tx = tid & 31, ty = tid >> 5;
    int col = blockIdx.x * 32 + tx;
    if (col >= ECOLS) return;
    int b0 = ty * 8;

    float acc[8];
#pragma unroll
    for (int r = 0; r < 8; r++) acc[r] = 0.f;

    if (col < 1728) {
        int i = col / 36, k = col - i * 36;
        const float* wp = W1 + (size_t)(144 + i * 48) * 36 + k;
#pragma unroll 4
        for (int j = 0; j < 48; j++) {
            float w = wp[j * 36];
            float4 a0 = *(const float4*)&As[j][b0];
            float4 a1 = *(const float4*)&As[j][b0 + 4];
            acc[0] += w * a0.x; acc[1] += w * a0.y; acc[2] += w * a0.z; acc[3] += w * a0.w;
            acc[4] += w * a1.x; acc[5] += w * a1.y; acc[6] += w * a1.z; acc[7] += w * a1.w;
        }
        float wcb = W1[(96 + i) * 36 + k] - W1[(48 + i) * 36 + k];
#pragma unroll
        for (int r = 0; r < 8; r++) acc[r] += wcb;
    } else {
        int k = col - 1728;
#pragma unroll 4
        for (int j = 0; j < 48; j++) {
            float w = W1[j * 36 + k] + W1[(48 + j) * 36 + k];
            float4 a0 = *(const float4*)&As[j][b0];
            float4 a1 = *(const float4*)&As[j][b0 + 4];
            acc[0] += w * a0.x; acc[1] += w * a0.y; acc[2] += w * a0.z; acc[3] += w * a0.w;
            acc[4] += w * a1.x; acc[5] += w * a1.y; acc[6] += w * a1.z; acc[7] += w * a1.w;
        }
        float bb = b1[k];
#pragma unroll
        for (int r = 0; r < 8; r++) acc[r] += bb;
    }
#pragma unroll
    for (int r = 0; r < 8; r++)
        g_Ec[(size_t)(b_base + b0 + r) * ECOLS + col] = acc[r];
}

// ============================================================================
// K2: h_pre[s,k,b] for KEPT s only. grid (100, 8): (s, b-group of 64).
// block 192 = 64 b_local x 3 k-quarters (12 k each).
// ============================================================================
__global__ void k2_hpre(const float* __restrict__ table,
                        const int* __restrict__ vg, const int* __restrict__ vsh,
                        const int* __restrict__ vc) {
    int s = blockIdx.x;
    if (!g_skeep[s]) return;
    __shared__ float vsS[64][49];   // padded: conflict-free broadcast
    int t = threadIdx.x;
    int b0 = blockIdx.y * 64;

    // gather behavior vectors for the 64 b at this s: 192 threads = 64 b x 3 ids
    {
        int bl = t / 3, which = t - bl * 3;
        int b = b0 + bl;
        int id = (which == 0) ? vg[b * SEQ + s] : (which == 1) ? vsh[b * SEQ + s] : vc[b * SEQ + s];
        const float4* row = (const float4*)(table + (size_t)id * DIM);
        float4 r0 = row[0], r1 = row[1], r2 = row[2], r3 = row[3];
        int i0 = which * 16;
        vsS[bl][i0 + 0] = r0.x; vsS[bl][i0 + 1] = r0.y; vsS[bl][i0 + 2] = r0.z; vsS[bl][i0 + 3] = r0.w;
        vsS[bl][i0 + 4] = r1.x; vsS[bl][i0 + 5] = r1.y; vsS[bl][i0 + 6] = r1.z; vsS[bl][i0 + 7] = r1.w;
        vsS[bl][i0 + 8] = r2.x; vsS[bl][i0 + 9] = r2.y; vsS[bl][i0 +10] = r2.z; vsS[bl][i0 +11] = r2.w;
        vsS[bl][i0 +12] = r3.x; vsS[bl][i0 +13] = r3.y; vsS[bl][i0 +14] = r3.z; vsS[bl][i0 +15] = r3.w;
    }
    __syncthreads();

    int kq = t % 3;             // 12 k-values each
    int bl = t / 3;
    int b = b0 + bl;
    const float* Eb = g_Ec + (size_t)b * ECOLS;
    float acc[12];
    {
        const float4* c4 = (const float4*)(Eb + 1728 + kq * 12);
        float4 a = c4[0], bb = c4[1], cc = c4[2];
        acc[0]=a.x; acc[1]=a.y; acc[2]=a.z; acc[3]=a.w;
        acc[4]=bb.x; acc[5]=bb.y; acc[6]=bb.z; acc[7]=bb.w;
        acc[8]=cc.x; acc[9]=cc.y; acc[10]=cc.z; acc[11]=cc.w;
    }
#pragma unroll 4
    for (int i = 0; i < 48; i++) {
        float v = vsS[bl][i];
        const float4* e = (const float4*)(Eb + i * 36 + kq * 12);
        float4 e0 = e[0], e1 = e[1], e2 = e[2];
        acc[0] += v * e0.x; acc[1] += v * e0.y; acc[2] += v * e0.z; acc[3] += v * e0.w;
        acc[4] += v * e1.x; acc[5] += v * e1.y; acc[6] += v * e1.z; acc[7] += v * e1.w;
        acc[8] += v * e2.x; acc[9] += v * e2.y; acc[10] += v * e2.z; acc[11] += v * e2.w;
    }
#pragma unroll
    for (int j = 0; j < 12; j++)
        g_h_skb[(size_t)(s * NH + kq * 12 + j) * BSZ + b] = acc[j];
}

// ============================================================================
// K3: Dice batch stats (over B) for KEPT s only. grid 100, block 128 (4 warps).
// warp w handles k = w*9 .. w*9+8.
// ============================================================================
__global__ void k3_act_stats() {
    int s = blockIdx.x;
    if (!g_skeep[s]) return;
    int t = threadIdx.x, w = t >> 5, lane = t & 31;
    for (int k = w * 9; k < w * 9 + 9; k++) {
        const float* row = g_h_skb + (size_t)(s * NH + k) * BSZ;
        float sum = 0.f, sq = 0.f;
#pragma unroll 4
        for (int i = 0; i < 16; i++) {
            float v = row[lane + 32 * i];
            sum += v; sq += v * v;
        }
#pragma unroll
        for (int o = 16; o; o >>= 1) {
            sum += __shfl_down_sync(0xffffffffu, sum, o);
            sq  += __shfl_down_sync(0xffffffffu, sq, o);
        }
        if (lane == 0) {
            float mu = sum * (1.f / 512.f);
            float var = sq * (1.f / 512.f) - mu * mu;
            g_mu_act[s * NH + k] = mu;
            g_isr_act[s * NH + k] = rsqrtf(var + 1e-3f);
        }
    }
}

// ============================================================================
// K4a: masked scores for all (b,s). grid 200, block 256. Only vg==0 computes.
// ============================================================================
__global__ void k4a_coef(const int* __restrict__ vg,
                         const float* __restrict__ alpha,
                         const float* __restrict__ wout,
                         const float* __restrict__ bout) {
    int idx = blockIdx.x * 256 + threadIdx.x;   // b*100+s
    if (idx >= BSZ * SEQ) return;
    int v = vg[idx];
    float coef = 0.f;
    if (v == 0) {
        int b = idx / SEQ, s = idx - b * SEQ;
        float acc = bout[0];
        for (int k = 0; k < NH; k++) {
            int r = s * NH + k;
            float x = g_h_skb[(size_t)r * BSZ + b];
            float xn = (x - g_mu_act[r]) * g_isr_act[r];
            float p = 1.f / (1.f + expf(-xn));
            acc += wout[k] * x * (p + alpha[k] * (1.f - p));
        }
        coef = acc;
    }
    g_coef[idx] = coef;
}

// ============================================================================
// K4b: x = [profile(128), x_inter(48)]. grid 512 (b), block 128.
// x_inter via ballot-scan of nonzero coefs (usually none).
// ============================================================================
__global__ void k4b_x(const float* __restrict__ table, IdPtrs ids,
                      const int* __restrict__ vg, const int* __restrict__ vsh,
                      const int* __restrict__ vc) {
    __shared__ float coefS[SEQ];
    __shared__ unsigned mS[4];
    int b = blockIdx.x, t = threadIdx.x;

    if (t < SEQ) coefS[t] = g_coef[b * SEQ + t];
    __syncthreads();
    {
        unsigned pred = (t < SEQ) && (coefS[t < SEQ ? t : 0] != 0.f);
        unsigned m = __ballot_sync(0xffffffffu, pred);
        if ((t & 31) == 0) mS[t >> 5] = m;
    }
    __syncthreads();

    // profile gather
    {
        int which = t >> 4;
        int id = ids.p[which][b];
        g_x[(size_t)b * COMB + t] = table[(size_t)id * DIM + (t & 15)];
    }
    // x_inter
    float acc = 0.f;
#pragma unroll
    for (int w4 = 0; w4 < 4; w4++) {
        unsigned m = mS[w4];
        while (m) {
            int s = w4 * 32 + __ffs(m) - 1;
            m &= m - 1;
            float c = coefS[s];
            if (t < F48) {
                int which = t >> 4;
                int id = (which == 0) ? vg[b * SEQ + s]
                       : (which == 1) ? vsh[b * SEQ + s] : vc[b * SEQ + s];
                acc += c * table[(size_t)id * DIM + (t & 15)];
            }
        }
    }
    if (t < F48) g_x[(size_t)b * COMB + 128 + t] = acc;
}

// ============================================================================
// K5: MLP1: y1 = LN(x @ W[176,200] + b). grid 32 (16 rows), block 256.
// ============================================================================
__global__ void k5_mlp1(const float* __restrict__ W, const float* __restrict__ bias,
                        const float* __restrict__ g, const float* __restrict__ beta) {
    __shared__ float xs[16 * COMB];
    __shared__ float ys[16][200];
    __shared__ float mu_s[16], isr_s[16];
    int tid = threadIdx.x;
    int b0 = blockIdx.x * 16;

    const float4* src = (const float4*)(g_x + (size_t)b0 * COMB);
    for (int p = tid; p < 16 * COMB / 4; p += 256) ((float4*)xs)[p] = src[p];
    __syncthreads();

    if (tid < 200) {
        float acc[16];
        float bb = bias[tid];
#pragma unroll
        for (int r = 0; r < 16; r++) acc[r] = bb;
        for (int j = 0; j < COMB; j++) {
            float w = W[j * 200 + tid];
#pragma unroll
            for (int r = 0; r < 16; r++) acc[r] += w * xs[r * COMB + j];
        }
#pragma unroll
        for (int r = 0; r < 16; r++) ys[r][tid] = acc[r];
    }
    __syncthreads();
    if (tid < 16) {
        float s = 0.f, q = 0.f;
        for (int c = 0; c < 200; c++) { float v = ys[tid][c]; s += v; q += v * v; }
        float mu = s * (1.f / 200.f);
        float var = q * (1.f / 200.f) - mu * mu;
        mu_s[tid] = mu; isr_s[tid] = rsqrtf(var + 1e-3f);
    }
    __syncthreads();
    if (tid < 200) {
        float gg = g[tid], be = beta[tid];
#pragma unroll
        for (int r = 0; r < 16; r++)
            g_y1[(size_t)(b0 + r) * 200 + tid] = (ys[r][tid] - mu_s[r]) * isr_s[r] * gg + be;
    }
}

// ============================================================================
// K6/K8: per-feature batch stats over B (sel 0 -> y1[200], sel 1 -> y2[80])
// ============================================================================
__global__ void k_feat_stats(int sel) {
    const float* src; int Fdim; float* mu; float* isr;
    if (sel == 0) { src = g_y1; Fdim = 200; mu = g_mu1; isr = g_isr1; }
    else          { src = g_y2; Fdim = 80;  mu = g_mu2; isr = g_isr2; }
    int f = blockIdx.x;
    int tid = threadIdx.x;
    float s = 0.f, q = 0.f;
    for (int b = tid; b < BSZ; b += 128) {
        float v = src[(size_t)b * Fdim + f];
        s += v; q += v * v;
    }
#pragma unroll
    for (int o = 16; o; o >>= 1) {
        s += __shfl_down_sync(0xffffffffu, s, o);
        q += __shfl_down_sync(0xffffffffu, q, o);
    }
    __shared__ float sh[8];
    int w = tid >> 5;
    if ((tid & 31) == 0) { sh[w] = s; sh[4 + w] = q; }
    __syncthreads();
    if (tid == 0) {
        s = sh[0] + sh[1] + sh[2] + sh[3];
        q = sh[4] + sh[5] + sh[6] + sh[7];
        float m = s * (1.f / 512.f);
        float var = q * (1.f / 512.f) - m * m;
        mu[f] = m; isr[f] = rsqrtf(var + 1e-3f);
    }
}

// ============================================================================
// K7: MLP2: y2 = LN(dice(y1) @ W[200,80] + b). grid 32, block 128.
// ============================================================================
__global__ void k7_mlp2(const float* __restrict__ alpha1, const float* __restrict__ W,
                        const float* __restrict__ bias,
                        const float* __restrict__ g, const float* __restrict__ beta) {
    __shared__ float hs[16 * 200];
    __shared__ float ys[16][80];
    __shared__ float mu_s[16], isr_s[16];
    int tid = threadIdx.x;
    int b0 = blockIdx.x * 16;

    for (int p = tid; p < 16 * 200; p += 128) {
        int f = p % 200;
        float v = g_y1[(size_t)b0 * 200 + p];
        float xn = (v - g_mu1[f]) * g_isr1[f];
        float pp = 1.f / (1.f + expf(-xn));
        hs[p] = v * (pp + alpha1[f] * (1.f - pp));
    }
    __syncthreads();

    if (tid < 80) {
        float acc[16];
        float bb = bias[tid];
#pragma unroll
        for (int r = 0; r < 16; r++) acc[r] = bb;
        for (int j = 0; j < 200; j++) {
            float w = W[j * 80 + tid];
#pragma unroll
            for (int r = 0; r < 16; r++) acc[r] += w * hs[r * 200 + j];
        }
#pragma unroll
        for (int r = 0; r < 16; r++) ys[r][tid] = acc[r];
    }
    __syncthreads();
    if (tid < 16) {
        float s = 0.f, q = 0.f;
        for (int c = 0; c < 80; c++) { float v = ys[tid][c]; s += v; q += v * v; }
        float mu = s * (1.f / 80.f);
        float var = q * (1.f / 80.f) - mu * mu;
        mu_s[tid] = mu; isr_s[tid] = rsqrtf(var + 1e-3f);
    }
    __syncthreads();
    if (tid < 80) {
        float gg = g[tid], be = beta[tid];
#pragma unroll
        for (int r = 0; r < 16; r++)
            g_y2[(size_t)(b0 + r) * 80 + tid] = (ys[r][tid] - mu_s[r]) * isr_s[r] * gg + be;
    }
}

// ============================================================================
// K9: out = softmax(dice(y2) @ W[80,2] + b). grid 2, block 256.
// ============================================================================
__global__ void k9_out(const float* __restrict__ alpha2, const float* __restrict__ W,
                       const float* __restrict__ bout, float* __restrict__ out) {
    int b = blockIdx.x * blockDim.x + threadIdx.x;
    if (b >= BSZ) return;
    float a0 = bout[0], a1 = bout[1];
#pragma unroll 4
    for (int k = 0; k < 80; k++) {
        float v = g_y2[(size_t)b * 80 + k];
        float xn = (v - g_mu2[k]) * g_isr2[k];
        float pp = 1.f / (1.f + expf(-xn));
        float h = v * (pp + alpha2[k] * (1.f - pp));
        a0 += h * W[k * 2];
        a1 += h * W[k * 2 + 1];
    }
    float m = fmaxf(a0, a1);
    float e0 = expf(a0 - m), e1 = expf(a1 - m);
    float inv = 1.f / (e0 + e1);
    out[b * 2] = e0 * inv;
    out[b * 2 + 1] = e1 * inv;
}

// ============================================================================
extern "C" void kernel_launch(void* const* d_in, const int* in_sizes, int n_in,
                              void* d_out, int out_size) {
    (void)in_sizes; (void)n_in; (void)out_size;
    const int* uid  = (const int*)d_in[0];
    const int* ut1  = (const int*)d_in[1];
    const int* ut2  = (const int*)d_in[2];
    const int* ut3  = (const int*)d_in[3];
    const int* ut4  = (const int*)d_in[4];
    const int* ig   = (const int*)d_in[5];
    const int* ish  = (const int*)d_in[6];
    const int* ic   = (const int*)d_in[7];
    const int* vg   = (const int*)d_in[8];
    const int* vsh  = (const int*)d_in[9];
    const int* vc   = (const int*)d_in[10];
    const float* table     = (const float*)d_in[11];
    const float* W_act1    = (const float*)d_in[12];
    const float* b_act1    = (const float*)d_in[13];
    const float* alpha_act = (const float*)d_in[14];
    const float* W_act_out = (const float*)d_in[15];
    const float* b_act_out = (const float*)d_in[16];
    const float* W_mlp1    = (const float*)d_in[17];
    const float* b_mlp1    = (const float*)d_in[18];
    const float* g_ln1     = (const float*)d_in[19];
    const float* beta_ln1  = (const float*)d_in[20];
    const float* alpha_m1  = (const float*)d_in[21];
    const float* W_mlp2    = (const float*)d_in[22];
    const float* b_mlp2    = (const float*)d_in[23];
    const float* g_ln2     = (const float*)d_in[24];
    const float* beta_ln2  = (const float*)d_in[25];
    const float* alpha_m2  = (const float*)d_in[26];
    const float* W_out     = (const float*)d_in[27];
    const float* b_out     = (const float*)d_in[28];
    float* out = (float*)d_out;

    IdPtrs ids;
    ids.p[0] = uid; ids.p[1] = ut1; ids.p[2] = ut2; ids.p[3] = ut3;
    ids.p[4] = ut4; ids.p[5] = ig;  ids.p[6] = ish; ids.p[7] = ic;

    k0_keep<<<SEQ, 128>>>(vg);
    k0b_any<<<1, 128>>>();
    k1_EC<<<dim3(56, 8), 256>>>(table, ig, ish, ic, W_act1, b_act1);
    k2_hpre<<<dim3(SEQ, 8), 192>>>(table, vg, vsh, vc);
    k3_act_stats<<<SEQ, 128>>>();
    k4a_coef<<<200, 256>>>(vg, alpha_act, W_act_out, b_act_out);
    k4b_x<<<BSZ, 128>>>(table, ids, vg, vsh, vc);
    k5_mlp1<<<32, 256>>>(W_mlp1, b_mlp1, g_ln1, beta_ln1);
    k_feat_stats<<<200, 128>>>(0);
    k7_mlp2<<<32, 128>>>(alpha_m1, W_mlp2, b_mlp2, g_ln2, beta_ln2);
    k_feat_stats<<<80, 128>>>(1);
    k9_out<<<2, 256>>>(alpha_m2, W_out, b_out, out);
}